// round 10
// baseline (speedup 1.0000x reference)
#include <cuda_runtime.h>
#include <cuda_bf16.h>
#include <mma.h>
#include <math.h>
#include <stdint.h>

using namespace nvcuda;

#define BTOT 512
#define NMEM 30
#define HW 1024
#define NGTH_ 15
#define TPBF 480

typedef unsigned long long u64;

__device__ __forceinline__ u64 dup2f(float v){u64 r;asm("mov.b64 %0,{%1,%1};":"=l"(r):"f"(v));return r;}
__device__ __forceinline__ void fma2(u64&d,u64 a,u64 b){asm("fma.rn.f32x2 %0,%1,%2,%0;":"+l"(d):"l"(a),"l"(b));}
__device__ __forceinline__ float2 unp2(u64 v){float lo,hi;asm("mov.b64 {%0,%1},%2;":"=f"(lo),"=f"(hi):"l"(v));return make_float2(lo,hi);}

__device__ float g_x1[(size_t)BTOT*225*64];   // pos-major [p][oc]
__device__ float g_x2[(size_t)BTOT*169*64];

// ---------------------------------------------------------------------------
// Kernel 1: fused stats + conv1 + bn + relu + pool -> g_x1 pos-major
// ---------------------------------------------------------------------------
__global__ __launch_bounds__(TPBF, 1) void stats_conv1_kernel(
    const float* __restrict__ ts, const float* __restrict__ ptm,
    const float* __restrict__ pmt, const float* __restrict__ piou,
    const void* __restrict__ mask_raw,
    const float* __restrict__ w1, const float* __restrict__ cb1,
    const float* __restrict__ g1, const float* __restrict__ bb1,
    const float* __restrict__ m1, const float* __restrict__ v1)
{
    const int b = blockIdx.x, tid = threadIdx.x, lane = tid & 31, wid = tid >> 5;
    __shared__ float smI[6528];       // 6 ch x 32 rows x 34 stride
    __shared__ float smW[3456];       // conv1 weights pair layout
    __shared__ float smE[128];        // folded scale/bias
    __shared__ float mf[NMEM], ow[NMEM], pmax[NMEM], warpmax[16], sc[16];

    unsigned int w0 = *(const unsigned int*)mask_raw;
    int mode = (w0 == 1u) ? 1 : ((w0 == 0x3F800000u) ? 2 : 0);

    if (tid == 0) {
        float run = 0.f, ca = 0.f, cg = 0.f, co = 0.f;
        for (int m = 0; m < NMEM; ++m) {
            int idx = b * NMEM + m; float f;
            if (mode == 1)      f = (((const int*)mask_raw)[idx] != 0) ? 1.f : 0.f;
            else if (mode == 2) f = (((const float*)mask_raw)[idx] != 0.f) ? 1.f : 0.f;
            else                f = (((const unsigned char*)mask_raw)[idx] != 0) ? 1.f : 0.f;
            run += f;
            float g = (run - 1.f < (float)NGTH_) ? f : 0.f;
            float o = f - g;
            mf[m] = f; ow[m] = o; ca += f; cg += g; co += o;
        }
        sc[7] = ca; sc[8] = cg; sc[9] = co;
        sc[10] = piou[b];
    }

    float tmax = -INFINITY;
    const float* tsb = ts + (size_t)b * HW;
    for (int p = tid; p < HW; p += TPBF) tmax = fmaxf(tmax, tsb[p]);
    #pragma unroll
    for (int off = 16; off > 0; off >>= 1) tmax = fmaxf(tmax, __shfl_xor_sync(0xffffffffu, tmax, off));
    if (lane == 0) warpmax[wid] = tmax;

    const float* ptmb = ptm + (size_t)b * NMEM * HW;
    for (int m = wid; m < NMEM; m += 15) {
        float mx = -INFINITY;
        const float* pr = ptmb + (size_t)m * HW;
        for (int p = lane; p < HW; p += 32) mx = fmaxf(mx, pr[p]);
        #pragma unroll
        for (int off = 16; off > 0; off >>= 1) mx = fmaxf(mx, __shfl_xor_sync(0xffffffffu, mx, off));
        if (lane == 0) pmax[m] = mx;
    }
    __syncthreads();

    if (wid == 0) {
        float v = (lane < 15) ? warpmax[lane] : -INFINITY;
        #pragma unroll
        for (int off = 16; off > 0; off >>= 1) v = fmaxf(v, __shfl_xor_sync(0xffffffffu, v, off));
        if (lane == 0) sc[0] = v;
    }
    if (wid == 1) {
        float v  = (lane < NMEM) ? pmax[lane] : 0.f;
        float fa = (lane < NMEM) ? mf[lane] : 0.f;
        float fo = (lane < NMEM) ? ow[lane] : 0.f;
        float fg = fa - fo;
        float sa = v*fa, ssa = v*v*fa, sg = v*fg, ssg = v*v*fg, so = v*fo, sso = v*v*fo;
        #pragma unroll
        for (int off = 16; off > 0; off >>= 1) {
            sa  += __shfl_xor_sync(0xffffffffu, sa, off);  ssa += __shfl_xor_sync(0xffffffffu, ssa, off);
            sg  += __shfl_xor_sync(0xffffffffu, sg, off);  ssg += __shfl_xor_sync(0xffffffffu, ssg, off);
            so  += __shfl_xor_sync(0xffffffffu, so, off);  sso += __shfl_xor_sync(0xffffffffu, sso, off);
        }
        if (lane == 0) {
            float ca = sc[7], cg = sc[8], co = sc[9];
            float mA = sa / ca; sc[1] = mA; sc[2] = sqrtf(fmaxf(ssa / ca - mA * mA, 0.f));
            float mG = sg / cg; sc[3] = mG; sc[4] = sqrtf(fmaxf(ssg / cg - mG * mG, 0.f));
            float mO = so / co; sc[5] = mO; sc[6] = sqrtf(fmaxf(sso / co - mO * mO, 0.f));
        }
    }
    __syncthreads();

    // per-pixel stats -> smI (stride-34 layout), ch order matches w1 ic 2..7
    {
        const float* pmtb = pmt + (size_t)b * NMEM * HW;
        const float ca = sc[7], co = sc[9];
        for (int p = tid; p < HW; p += TPBF) {
            float sa = 0, ssa = 0, sg = 0, ssg = 0, so = 0, sso = 0;
            #pragma unroll 5
            for (int m = 0; m < NMEM; ++m) {
                float v = pmtb[(size_t)m * HW + p];
                float fa = mf[m], fo = ow[m];
                sa += v * fa; ssa += v * v * fa;
                if (m < NGTH_) { sg += v; ssg += v * v; }
                so += v * fo; sso += v * v * fo;
            }
            float mA = sa / ca, sA = sqrtf(fmaxf(ssa / ca - mA * mA, 0.f));
            float mG = sg * (1.f / NGTH_), sG = sqrtf(fmaxf(ssg * (1.f / NGTH_) - mG * mG, 0.f));
            float mO = so / co, sO = sqrtf(fmaxf(sso / co - mO * mO, 0.f));
            int r = p >> 5, x = p & 31, base = r * 34 + x;
            smI[0 * 1088 + base] = mA; smI[1 * 1088 + base] = sA;
            smI[2 * 1088 + base] = mG; smI[3 * 1088 + base] = sG;
            smI[4 * 1088 + base] = mO; smI[5 * 1088 + base] = sO;
        }
        for (int i = tid; i < 64 * 6 * 9; i += TPBF) {
            int oc = i / 54; int r = i - oc * 54;
            int c = r / 9; int t = r - c * 9;
            smW[((oc >> 1) * 6 + c) * 18 + t * 2 + (oc & 1)] = w1[oc * 126 + (c + 2) * 9 + t];
        }
        if (tid < 64) {
            float cst[8] = {sc[0], sc[10], sc[1], sc[2], sc[3], sc[4], sc[5], sc[6]};
            float extra = 0.f;
            #pragma unroll
            for (int j = 0; j < 8; ++j) {
                int ic = (j < 2) ? j : (j + 6);
                const float* wb = w1 + tid * 126 + ic * 9;
                float s9 = 0.f;
                #pragma unroll
                for (int t = 0; t < 9; ++t) s9 += wb[t];
                extra += cst[j] * s9;
            }
            float s = g1[tid] * rsqrtf(v1[tid] + 1e-5f);
            smE[tid] = s;
            smE[64 + tid] = s * (extra + cb1[tid] - m1[tid]) + bb1[tid];
        }
    }
    __syncthreads();

    // conv1 scalar (validated R3 stage-1), out pos-major
    float* xo = g_x1 + (size_t)b * 225 * 64;
    #pragma unroll
    for (int itb = 0; itb < 2; ++itb) {
        int it = tid + itb * TPBF;
        int ocg = it / 60;
        int r = it - ocg * 60;
        int pr = r >> 2, pq = r & 3;
        int x0 = 8 * pq, r0 = 2 * pr;

        u64 acc[2][2][8];
        #pragma unroll
        for (int p = 0; p < 2; ++p)
            #pragma unroll
            for (int e = 0; e < 2; ++e)
                #pragma unroll
                for (int c = 0; c < 8; ++c) acc[p][e][c] = 0ull;

        for (int ch = 0; ch < 6; ++ch) {
            const float* ib = &smI[ch * 1088 + r0 * 34 + x0];
            const u64* wb0 = (const u64*)&smW[((ocg * 2) * 6 + ch) * 18];
            const u64* wb1 = (const u64*)&smW[((ocg * 2 + 1) * 6 + ch) * 18];
            #pragma unroll
            for (int ir = 0; ir < 4; ++ir) {
                u64 d[10];
                #pragma unroll
                for (int q = 0; q < 5; ++q) {
                    float2 a = *(const float2*)(ib + ir * 34 + 2 * q);
                    d[2*q] = dup2f(a.x); d[2*q+1] = dup2f(a.y);
                }
                #pragma unroll
                for (int kx = 0; kx < 3; ++kx) {
                    if (ir <= 2) {
                        u64 wa = wb0[ir*3+kx], wc = wb1[ir*3+kx];
                        #pragma unroll
                        for (int c = 0; c < 8; ++c) { fma2(acc[0][0][c], wa, d[c+kx]); fma2(acc[1][0][c], wc, d[c+kx]); }
                    }
                    if (ir >= 1) {
                        u64 wa = wb0[(ir-1)*3+kx], wc = wb1[(ir-1)*3+kx];
                        #pragma unroll
                        for (int c = 0; c < 8; ++c) { fma2(acc[0][1][c], wa, d[c+kx]); fma2(acc[1][1][c], wc, d[c+kx]); }
                    }
                }
            }
        }
        #pragma unroll
        for (int p = 0; p < 2; ++p) {
            int oc0 = ocg * 4 + 2 * p;
            float s0 = smE[oc0], bi0 = smE[64+oc0];
            float s1 = smE[oc0+1], bi1 = smE[64+oc0+1];
            #pragma unroll
            for (int j = 0; j < 4; ++j) {
                int pt = 4 * pq + j;
                if (pt < 15) {
                    float2 a = unp2(acc[p][0][2*j]), bq = unp2(acc[p][0][2*j+1]);
                    float2 cq = unp2(acc[p][1][2*j]), e = unp2(acc[p][1][2*j+1]);
                    float lo = fmaxf(fmaxf(fmaxf(s0*a.x+bi0,0.f), fmaxf(s0*bq.x+bi0,0.f)),
                                     fmaxf(fmaxf(s0*cq.x+bi0,0.f), fmaxf(s0*e.x+bi0,0.f)));
                    float hi = fmaxf(fmaxf(fmaxf(s1*a.y+bi1,0.f), fmaxf(s1*bq.y+bi1,0.f)),
                                     fmaxf(fmaxf(s1*cq.y+bi1,0.f), fmaxf(s1*e.y+bi1,0.f)));
                    int pos = pr * 15 + pt;
                    xo[pos * 64 + oc0] = lo;
                    xo[pos * 64 + oc0 + 1] = hi;
                }
            }
        }
    }
}

// ---------------------------------------------------------------------------
// Kernel 2/3: conv 64->64 via 9 tap-GEMMs, bf16 wmma 3-pass, 2-phase W preload.
// FUSE4: keep conv3 output in smem, run conv4 + global max, write out[b].
// ---------------------------------------------------------------------------
template<int IN_W, int OUT_W, bool FUSE4>
__global__ __launch_bounds__(512, 1) void convmma_kernel(
    const float* __restrict__ xin_base, float* __restrict__ xout_base,
    const float* __restrict__ wsrc, const float* __restrict__ cb,
    const float* __restrict__ gg, const float* __restrict__ bbv,
    const float* __restrict__ mmv, const float* __restrict__ vvv,
    const float* __restrict__ w4, const float* __restrict__ cb4,
    float* __restrict__ out)
{
    constexpr int INROWS = IN_W * IN_W;
    constexpr int MMAX = (OUT_W - 1) * IN_W + OUT_W;
    constexpr int MTILES = (MMAX + 15) / 16;
    constexpr int XROWS = MTILES * 16 + 2 * IN_W + 2;
    constexpr int NUNITS = MTILES * 2;
    constexpr int LDX = 72, LDW = 72;
    constexpr int OXH = 0;
    constexpr int OXL = OXH + XROWS * LDX * 2;
    constexpr int OW_H = OXL + XROWS * LDX * 2;
    constexpr int OW_L = OW_H + 5 * 64 * LDW * 2;
    constexpr int OSB  = OW_L + 5 * 64 * LDW * 2;

    extern __shared__ char smc[];
    __nv_bfloat16* Xh = (__nv_bfloat16*)(smc + OXH);
    __nv_bfloat16* Xl = (__nv_bfloat16*)(smc + OXL);
    __nv_bfloat16* Wh = (__nv_bfloat16*)(smc + OW_H);
    __nv_bfloat16* Wl = (__nv_bfloat16*)(smc + OW_L);
    float* sbs = (float*)(smc + OSB);
    __shared__ float ws4[576];
    __shared__ float red[16];

    const int b = blockIdx.x, tid = threadIdx.x, wid = tid >> 5, lane = tid & 31;
    const float* xin = xin_base + (size_t)b * INROWS * 64;

    for (int i = tid; i < INROWS * 64; i += 512) {
        int p = i >> 6, c = i & 63;
        float v = xin[i];
        __nv_bfloat16 h = __float2bfloat16(v);
        Xh[p * LDX + c] = h;
        Xl[p * LDX + c] = __float2bfloat16(v - __bfloat162float(h));
    }
    for (int i = tid; i < (XROWS - INROWS) * 64; i += 512) {
        int p = INROWS + (i >> 6), c = i & 63;
        Xh[p * LDX + c] = __float2bfloat16(0.f);
        Xl[p * LDX + c] = __float2bfloat16(0.f);
    }
    if (tid < 64) {
        float s = gg[tid] * rsqrtf(vvv[tid] + 1e-5f);
        sbs[tid] = s;
        sbs[64 + tid] = s * (cb[tid] - mmv[tid]) + bbv[tid];
    }

    wmma::fragment<wmma::accumulator, 16, 16, 16, float> acc[2][2];
    #pragma unroll
    for (int u = 0; u < 2; ++u)
        #pragma unroll
        for (int n = 0; n < 2; ++n)
            wmma::fill_fragment(acc[u][n], 0.f);

    #pragma unroll
    for (int ph = 0; ph < 2; ++ph) {
        const int t0 = ph ? 5 : 0, NT = ph ? 4 : 5;
        __syncthreads();
        for (int i = tid; i < 64 * 64 * NT; i += 512) {
            int oc = i / (64 * NT); int r = i - oc * (64 * NT);
            int ic = r / NT, tt = r - ic * NT;
            float v = wsrc[oc * 576 + ic * 9 + t0 + tt];
            __nv_bfloat16 h = __float2bfloat16(v);
            Wh[(tt * 64 + ic) * LDW + oc] = h;
            Wl[(tt * 64 + ic) * LDW + oc] = __float2bfloat16(v - __bfloat162float(h));
        }
        __syncthreads();

        for (int tt = 0; tt < NT; ++tt) {
            int tap = t0 + tt;
            int toff = (tap / 3) * IN_W + (tap - (tap / 3) * 3);
            #pragma unroll
            for (int un = 0; un < 2; ++un) {
                int u = wid + 16 * un;
                if (u < NUNITS) {
                    int mt = u >> 1, nh = u & 1;
                    const __nv_bfloat16* A0 = Xh + (mt * 16 + toff) * LDX;
                    const __nv_bfloat16* A1 = Xl + (mt * 16 + toff) * LDX;
                    #pragma unroll
                    for (int k = 0; k < 4; ++k) {
                        wmma::fragment<wmma::matrix_a, 16, 16, 16, __nv_bfloat16, wmma::row_major> ah, al;
                        wmma::load_matrix_sync(ah, A0 + k * 16, LDX);
                        wmma::load_matrix_sync(al, A1 + k * 16, LDX);
                        #pragma unroll
                        for (int nt = 0; nt < 2; ++nt) {
                            wmma::fragment<wmma::matrix_b, 16, 16, 16, __nv_bfloat16, wmma::row_major> bh, bl;
                            const __nv_bfloat16* B0 = Wh + (tt * 64 + k * 16) * LDW + nh * 32 + nt * 16;
                            const __nv_bfloat16* B1 = Wl + (tt * 64 + k * 16) * LDW + nh * 32 + nt * 16;
                            wmma::load_matrix_sync(bh, B0, LDW);
                            wmma::load_matrix_sync(bl, B1, LDW);
                            wmma::mma_sync(acc[un][nt], ah, bh, acc[un][nt]);
                            wmma::mma_sync(acc[un][nt], ah, bl, acc[un][nt]);
                            wmma::mma_sync(acc[un][nt], al, bh, acc[un][nt]);
                        }
                    }
                }
            }
        }
    }

    // epilogue (patch + x3s alias over W region — mainloop done)
    __syncthreads();
    float* patch = (float*)(smc + OW_H) + wid * 16 * 36;
    float* x3s = (float*)(smc + OW_H + 40960);
    float* xout = FUSE4 ? nullptr : (xout_base + (size_t)b * OUT_W * OUT_W * 64);
    if (FUSE4)
        for (int i = tid; i < 576; i += 512) ws4[i] = w4[i];

    #pragma unroll
    for (int un = 0; un < 2; ++un) {
        int u = wid + 16 * un;
        if (u < NUNITS) {
            int mt = u >> 1, nh = u & 1;
            wmma::store_matrix_sync(patch,      acc[un][0], 36, wmma::mem_row_major);
            wmma::store_matrix_sync(patch + 16, acc[un][1], 36, wmma::mem_row_major);
            __syncwarp();
            int r = lane & 15, ch = (lane >> 4) * 16;
            int p = mt * 16 + r;
            int y = p / IN_W, x = p - y * IN_W;
            if (y < OUT_W && x < OUT_W) {
                int orow = y * OUT_W + x;
                #pragma unroll
                for (int j = 0; j < 16; ++j) {
                    int c = nh * 32 + ch + j;
                    float v = fmaxf(sbs[c] * patch[r * 36 + ch + j] + sbs[64 + c], 0.f);
                    if (FUSE4) x3s[orow * 68 + c] = v;
                    else       xout[orow * 64 + c] = v;
                }
            }
            __syncwarp();
        }
    }

    if (FUSE4) {
        __syncthreads();
        float lm = -INFINITY;
        if (tid < 81) {
            int y = tid / 9, x = tid - (tid / 9) * 9;
            float a = 0.f;
            #pragma unroll
            for (int ky = 0; ky < 3; ++ky)
                #pragma unroll
                for (int kx = 0; kx < 3; ++kx) {
                    const float* row = x3s + ((y + ky) * OUT_W + (x + kx)) * 68;
                    int t = ky * 3 + kx;
                    for (int ic = 0; ic < 64; ++ic)
                        a += row[ic] * ws4[ic * 9 + t];
                }
            lm = a;
        }
        #pragma unroll
        for (int off = 16; off > 0; off >>= 1) lm = fmaxf(lm, __shfl_xor_sync(0xffffffffu, lm, off));
        if (lane == 0) red[wid] = lm;
        __syncthreads();
        if (tid == 0) {
            float v = -INFINITY;
            #pragma unroll
            for (int i = 0; i < 16; ++i) v = fmaxf(v, red[i]);
            out[b] = v + cb4[0];
        }
    }
}

// ---------------------------------------------------------------------------
extern "C" void kernel_launch(void* const* d_in, const int* in_sizes, int n_in,
                              void* d_out, int out_size)
{
    // dynamic smem: conv2 XROWS=240 -> 69120 + 92160 + 512 = 161792
    //               conv3 XROWS=172 -> 49536 + 92160 + 512 = 142208
    const int S2 = 161792;
    const int S3 = 142208;
    static float *p1 = nullptr, *p2 = nullptr;
    if (!p1) {
        cudaGetSymbolAddress((void**)&p1, g_x1);
        cudaGetSymbolAddress((void**)&p2, g_x2);
        cudaFuncSetAttribute(convmma_kernel<15,13,false>, cudaFuncAttributeMaxDynamicSharedMemorySize, S2);
        cudaFuncSetAttribute(convmma_kernel<13,11,true>,  cudaFuncAttributeMaxDynamicSharedMemorySize, S3);
    }

    stats_conv1_kernel<<<BTOT, TPBF>>>(
        (const float*)d_in[0], (const float*)d_in[1],
        (const float*)d_in[2], (const float*)d_in[3], d_in[4],
        (const float*)d_in[5],  (const float*)d_in[6],
        (const float*)d_in[7],  (const float*)d_in[8],
        (const float*)d_in[9],  (const float*)d_in[10]);

    convmma_kernel<15,13,false><<<BTOT, 512, S2>>>(
        p1, p2,
        (const float*)d_in[11], (const float*)d_in[12],
        (const float*)d_in[13], (const float*)d_in[14],
        (const float*)d_in[15], (const float*)d_in[16],
        nullptr, nullptr, nullptr);

    convmma_kernel<13,11,true><<<BTOT, 512, S3>>>(
        p2, nullptr,
        (const float*)d_in[17], (const float*)d_in[18],
        (const float*)d_in[19], (const float*)d_in[20],
        (const float*)d_in[21], (const float*)d_in[22],
        (const float*)d_in[23], (const float*)d_in[24],
        (float*)d_out);
}

// round 11
// speedup vs baseline: 1.0325x; 1.0325x over previous
#include <cuda_runtime.h>
#include <cuda_bf16.h>
#include <mma.h>
#include <math.h>
#include <stdint.h>

using namespace nvcuda;

#define BTOT 512
#define NMEM 30
#define HW 1024
#define NGTH_ 15

typedef unsigned long long u64;

__device__ __forceinline__ u64 dup2f(float v){u64 r;asm("mov.b64 %0,{%1,%1};":"=l"(r):"f"(v));return r;}
__device__ __forceinline__ void fma2(u64&d,u64 a,u64 b){asm("fma.rn.f32x2 %0,%1,%2,%0;":"+l"(d):"l"(a),"l"(b));}
__device__ __forceinline__ float2 unp2(u64 v){float lo,hi;asm("mov.b64 {%0,%1},%2;":"=f"(lo),"=f"(hi):"l"(v));return make_float2(lo,hi);}

__device__ float g_inp6[(size_t)BTOT*6*HW];
__device__ float g_cst[(size_t)BTOT*8];
__device__ float g_x1[(size_t)BTOT*225*64];   // pos-major [p][oc]
__device__ float g_x2[(size_t)BTOT*169*64];
__device__ __nv_bfloat16 g_wh[2*9*4096];      // [conv][tap][ic][oc] hi
__device__ __nv_bfloat16 g_wl[2*9*4096];      // lo

// ---------------------------------------------------------------------------
// Kernel 0: weight prep — w2/w3 -> bf16 hi/lo, tap-major coalesced layout
// ---------------------------------------------------------------------------
__global__ __launch_bounds__(256) void wprep_kernel(
    const float* __restrict__ w2, const float* __restrict__ w3)
{
    int i = blockIdx.x * 256 + threadIdx.x;
    if (i < 2 * 9 * 4096) {
        int conv = i / 36864, r = i - conv * 36864;
        int tap = r >> 12, idx = r & 4095;
        int ic = idx >> 6, oc = idx & 63;
        const float* w = conv ? w3 : w2;
        float v = w[oc * 576 + ic * 9 + tap];
        __nv_bfloat16 h = __float2bfloat16(v);
        g_wh[i] = h;
        g_wl[i] = __float2bfloat16(v - __bfloat162float(h));
    }
}

// ---------------------------------------------------------------------------
// Kernel 1: stats — 1024 threads (1/pixel), high-MLP
// ---------------------------------------------------------------------------
__global__ __launch_bounds__(1024) void stats_kernel(
    const float* __restrict__ ts, const float* __restrict__ ptm,
    const float* __restrict__ pmt, const float* __restrict__ piou,
    const void* __restrict__ mask_raw)
{
    const int b = blockIdx.x, tid = threadIdx.x, lane = tid & 31, wid = tid >> 5;
    __shared__ float mf[NMEM], ow[NMEM], pmax[NMEM], warpmax[32], sc[16];

    unsigned int w0 = *(const unsigned int*)mask_raw;
    int mode = (w0 == 1u) ? 1 : ((w0 == 0x3F800000u) ? 2 : 0);

    if (tid == 0) {
        float run = 0.f, ca = 0.f, cg = 0.f, co = 0.f;
        for (int m = 0; m < NMEM; ++m) {
            int idx = b * NMEM + m; float f;
            if (mode == 1)      f = (((const int*)mask_raw)[idx] != 0) ? 1.f : 0.f;
            else if (mode == 2) f = (((const float*)mask_raw)[idx] != 0.f) ? 1.f : 0.f;
            else                f = (((const unsigned char*)mask_raw)[idx] != 0) ? 1.f : 0.f;
            run += f;
            float g = (run - 1.f < (float)NGTH_) ? f : 0.f;
            float o = f - g;
            mf[m] = f; ow[m] = o; ca += f; cg += g; co += o;
        }
        sc[7] = ca; sc[8] = cg; sc[9] = co;
    }

    // ts max (1 load/thread)
    {
        float v = ts[(size_t)b * HW + tid];
        #pragma unroll
        for (int off = 16; off > 0; off >>= 1) v = fmaxf(v, __shfl_xor_sync(0xffffffffu, v, off));
        if (lane == 0) warpmax[wid] = v;
    }

    // ptm max: warp m (m<30), 32 coalesced loads/lane
    if (wid < NMEM) {
        const float* pr = ptm + (size_t)b * NMEM * HW + (size_t)wid * HW;
        float mx = -INFINITY;
        #pragma unroll
        for (int k = 0; k < 32; ++k) mx = fmaxf(mx, pr[lane + 32 * k]);
        #pragma unroll
        for (int off = 16; off > 0; off >>= 1) mx = fmaxf(mx, __shfl_xor_sync(0xffffffffu, mx, off));
        if (lane == 0) pmax[wid] = mx;
    }
    __syncthreads();

    if (wid == 0) {
        float v = warpmax[lane];
        #pragma unroll
        for (int off = 16; off > 0; off >>= 1) v = fmaxf(v, __shfl_xor_sync(0xffffffffu, v, off));
        if (lane == 0) sc[0] = v;
    }
    if (wid == 1) {
        float v  = (lane < NMEM) ? pmax[lane] : 0.f;
        float fa = (lane < NMEM) ? mf[lane] : 0.f;
        float fo = (lane < NMEM) ? ow[lane] : 0.f;
        float fg = fa - fo;
        float sa = v*fa, ssa = v*v*fa, sg = v*fg, ssg = v*v*fg, so = v*fo, sso = v*v*fo;
        #pragma unroll
        for (int off = 16; off > 0; off >>= 1) {
            sa  += __shfl_xor_sync(0xffffffffu, sa, off);  ssa += __shfl_xor_sync(0xffffffffu, ssa, off);
            sg  += __shfl_xor_sync(0xffffffffu, sg, off);  ssg += __shfl_xor_sync(0xffffffffu, ssg, off);
            so  += __shfl_xor_sync(0xffffffffu, so, off);  sso += __shfl_xor_sync(0xffffffffu, sso, off);
        }
        if (lane == 0) {
            float ca = sc[7], cg = sc[8], co = sc[9];
            float mA = sa / ca; sc[1] = mA; sc[2] = sqrtf(fmaxf(ssa / ca - mA * mA, 0.f));
            float mG = sg / cg; sc[3] = mG; sc[4] = sqrtf(fmaxf(ssg / cg - mG * mG, 0.f));
            float mO = so / co; sc[5] = mO; sc[6] = sqrtf(fmaxf(sso / co - mO * mO, 0.f));
        }
    }
    __syncthreads();

    if (tid == 0) {
        float* c = g_cst + (size_t)b * 8;
        c[0] = sc[0]; c[1] = piou[b]; c[2] = sc[1]; c[3] = sc[2];
        c[4] = sc[3]; c[5] = sc[4];   c[6] = sc[5]; c[7] = sc[6];
    }

    // per-pixel pmt stats: 1 thread = 1 pixel, fully unrolled 30 loads
    {
        const float* pmtb = pmt + (size_t)b * NMEM * HW + tid;
        const float ca = sc[7], co = sc[9];
        float sa = 0, ssa = 0, sg = 0, ssg = 0, so = 0, sso = 0;
        #pragma unroll
        for (int m = 0; m < NMEM; ++m) {
            float v = pmtb[(size_t)m * HW];
            float fa = mf[m], fo = ow[m];
            sa += v * fa; ssa += v * v * fa;
            if (m < NGTH_) { sg += v; ssg += v * v; }
            so += v * fo; sso += v * v * fo;
        }
        float mA = sa / ca, sA = sqrtf(fmaxf(ssa / ca - mA * mA, 0.f));
        float mG = sg * (1.f / NGTH_), sG = sqrtf(fmaxf(ssg * (1.f / NGTH_) - mG * mG, 0.f));
        float mO = so / co, sO = sqrtf(fmaxf(sso / co - mO * mO, 0.f));
        float* ob = g_inp6 + (size_t)b * 6 * HW + tid;
        ob[0*HW] = mA; ob[1*HW] = sA; ob[2*HW] = mG;
        ob[3*HW] = sG; ob[4*HW] = mO; ob[5*HW] = sO;
    }
}

// ---------------------------------------------------------------------------
// Kernel 2: conv1 + bn + relu + pool -> g_x1 pos-major (validated R9)
// ---------------------------------------------------------------------------
#define TPB1 480
__global__ __launch_bounds__(TPB1, 1) void conv1_kernel(
    const float* __restrict__ w1, const float* __restrict__ cb1,
    const float* __restrict__ g1, const float* __restrict__ bb1,
    const float* __restrict__ m1, const float* __restrict__ v1)
{
    __shared__ float sm[6528 + 3456 + 128];
    const int IW_ = 6528, IE_ = 9984;
    const int b = blockIdx.x, tid = threadIdx.x;

    {
        const float* src = g_inp6 + (size_t)b * 6 * HW;
        for (int i = tid; i < 6 * HW; i += TPB1) {
            int c = i >> 10; int rem = i & 1023;
            sm[c * 1088 + (rem >> 5) * 34 + (rem & 31)] = src[i];
        }
        for (int i = tid; i < 64 * 6 * 9; i += TPB1) {
            int oc = i / 54; int r = i - oc * 54;
            int c = r / 9; int t = r - c * 9;
            sm[IW_ + ((oc >> 1) * 6 + c) * 18 + t * 2 + (oc & 1)] = w1[oc * 126 + (c + 2) * 9 + t];
        }
        if (tid < 64) {
            const float* cst = g_cst + (size_t)b * 8;
            float extra = 0.f;
            #pragma unroll
            for (int j = 0; j < 8; ++j) {
                int ic = (j < 2) ? j : (j + 6);
                const float* wb = w1 + tid * 126 + ic * 9;
                float s9 = 0.f;
                #pragma unroll
                for (int t = 0; t < 9; ++t) s9 += wb[t];
                extra += cst[j] * s9;
            }
            float s = g1[tid] * rsqrtf(v1[tid] + 1e-5f);
            sm[IE_ + tid] = s;
            sm[IE_ + 64 + tid] = s * (extra + cb1[tid] - m1[tid]) + bb1[tid];
        }
    }
    __syncthreads();

    float* xo = g_x1 + (size_t)b * 225 * 64;
    #pragma unroll
    for (int itb = 0; itb < 2; ++itb) {
        int it = tid + itb * TPB1;
        int ocg = it / 60;
        int r = it - ocg * 60;
        int pr = r >> 2, pq = r & 3;
        int x0 = 8 * pq, r0 = 2 * pr;

        u64 acc[2][2][8];
        #pragma unroll
        for (int p = 0; p < 2; ++p)
            #pragma unroll
            for (int e = 0; e < 2; ++e)
                #pragma unroll
                for (int c = 0; c < 8; ++c) acc[p][e][c] = 0ull;

        for (int ch = 0; ch < 6; ++ch) {
            const float* ib = &sm[ch * 1088 + r0 * 34 + x0];
            const u64* wb0 = (const u64*)&sm[IW_ + ((ocg * 2) * 6 + ch) * 18];
            const u64* wb1 = (const u64*)&sm[IW_ + ((ocg * 2 + 1) * 6 + ch) * 18];
            #pragma unroll
            for (int ir = 0; ir < 4; ++ir) {
                u64 d[10];
                #pragma unroll
                for (int q = 0; q < 5; ++q) {
                    float2 a = *(const float2*)(ib + ir * 34 + 2 * q);
                    d[2*q] = dup2f(a.x); d[2*q+1] = dup2f(a.y);
                }
                #pragma unroll
                for (int kx = 0; kx < 3; ++kx) {
                    if (ir <= 2) {
                        u64 wa = wb0[ir*3+kx], wc = wb1[ir*3+kx];
                        #pragma unroll
                        for (int c = 0; c < 8; ++c) { fma2(acc[0][0][c], wa, d[c+kx]); fma2(acc[1][0][c], wc, d[c+kx]); }
                    }
                    if (ir >= 1) {
                        u64 wa = wb0[(ir-1)*3+kx], wc = wb1[(ir-1)*3+kx];
                        #pragma unroll
                        for (int c = 0; c < 8; ++c) { fma2(acc[0][1][c], wa, d[c+kx]); fma2(acc[1][1][c], wc, d[c+kx]); }
                    }
                }
            }
        }
        #pragma unroll
        for (int p = 0; p < 2; ++p) {
            int oc0 = ocg * 4 + 2 * p;
            float s0 = sm[IE_+oc0], bi0 = sm[IE_+64+oc0];
            float s1 = sm[IE_+oc0+1], bi1 = sm[IE_+64+oc0+1];
            #pragma unroll
            for (int j = 0; j < 4; ++j) {
                int pt = 4 * pq + j;
                if (pt < 15) {
                    float2 a = unp2(acc[p][0][2*j]), bq = unp2(acc[p][0][2*j+1]);
                    float2 cq = unp2(acc[p][1][2*j]), e = unp2(acc[p][1][2*j+1]);
                    float lo = fmaxf(fmaxf(fmaxf(s0*a.x+bi0,0.f), fmaxf(s0*bq.x+bi0,0.f)),
                                     fmaxf(fmaxf(s0*cq.x+bi0,0.f), fmaxf(s0*e.x+bi0,0.f)));
                    float hi = fmaxf(fmaxf(fmaxf(s1*a.y+bi1,0.f), fmaxf(s1*bq.y+bi1,0.f)),
                                     fmaxf(fmaxf(s1*cq.y+bi1,0.f), fmaxf(s1*e.y+bi1,0.f)));
                    int pos = pr * 15 + pt;
                    xo[pos * 64 + oc0] = lo;
                    xo[pos * 64 + oc0 + 1] = hi;
                }
            }
        }
    }
}

// ---------------------------------------------------------------------------
// Kernel 3/4: conv 64->64, 9 tap-GEMMs, bf16 wmma 3-pass, 1 unit/warp,
// coalesced pre-transposed weights. FUSE4: conv4 + global max in-kernel.
// ---------------------------------------------------------------------------
template<int IN_W, int OUT_W, bool FUSE4, int TPB>
__global__ __launch_bounds__(TPB, 1) void convmma_kernel(
    const float* __restrict__ xin_base, float* __restrict__ xout_base,
    int woff,
    const float* __restrict__ cb,
    const float* __restrict__ gg, const float* __restrict__ bbv,
    const float* __restrict__ mmv, const float* __restrict__ vvv,
    const float* __restrict__ w4, const float* __restrict__ cb4,
    float* __restrict__ out)
{
    constexpr int INROWS = IN_W * IN_W;
    constexpr int MMAX = (OUT_W - 1) * IN_W + OUT_W;
    constexpr int MTILES = (MMAX + 15) / 16;
    constexpr int XROWS = ((MTILES * 16 + 2 * IN_W + 2 + 15) / 16) * 16;
    constexpr int NUNITS = MTILES * 2;       // == TPB/32
    constexpr int LDX = 72;
    constexpr int OXH = 0;
    constexpr int OXL = OXH + XROWS * LDX * 2;
    constexpr int OWH = OXL + XROWS * LDX * 2;
    constexpr int OWL = OWH + 64 * LDX * 2;
    constexpr int OSB = OWL + 64 * LDX * 2;
    constexpr int OPATCH = OSB + 512;
    constexpr int OX3 = OPATCH + NUNITS * 16 * 36 * 4;

    extern __shared__ char smc[];
    __nv_bfloat16* Xh = (__nv_bfloat16*)(smc + OXH);
    __nv_bfloat16* Xl = (__nv_bfloat16*)(smc + OXL);
    __nv_bfloat16* Wh = (__nv_bfloat16*)(smc + OWH);
    __nv_bfloat16* Wl = (__nv_bfloat16*)(smc + OWL);
    float* sbs = (float*)(smc + OSB);
    __shared__ float ws4[576];
    __shared__ float red[32];

    const int b = blockIdx.x, tid = threadIdx.x, wid = tid >> 5, lane = tid & 31;
    const float* xin = xin_base + (size_t)b * INROWS * 64;

    for (int i = tid; i < INROWS * 64; i += TPB) {
        int p = i >> 6, c = i & 63;
        float v = xin[i];
        __nv_bfloat16 h = __float2bfloat16(v);
        Xh[p * LDX + c] = h;
        Xl[p * LDX + c] = __float2bfloat16(v - __bfloat162float(h));
    }
    for (int i = tid; i < (XROWS - INROWS) * 64; i += TPB) {
        int p = INROWS + (i >> 6), c = i & 63;
        Xh[p * LDX + c] = __float2bfloat16(0.f);
        Xl[p * LDX + c] = __float2bfloat16(0.f);
    }
    if (tid < 64) {
        float s = gg[tid] * rsqrtf(vvv[tid] + 1e-5f);
        sbs[tid] = s;
        sbs[64 + tid] = s * (cb[tid] - mmv[tid]) + bbv[tid];
    }

    const int mt = wid >> 1, nh = wid & 1;

    wmma::fragment<wmma::accumulator, 16, 16, 16, float> acc[2];
    wmma::fill_fragment(acc[0], 0.f);
    wmma::fill_fragment(acc[1], 0.f);

    for (int tap = 0; tap < 9; ++tap) {
        __syncthreads();
        {
            const __nv_bfloat16* sh = g_wh + woff + tap * 4096;
            const __nv_bfloat16* sl = g_wl + woff + tap * 4096;
            for (int i = tid; i < 4096; i += TPB) {
                int ic = i >> 6, oc = i & 63;
                Wh[ic * LDX + oc] = sh[i];
                Wl[ic * LDX + oc] = sl[i];
            }
        }
        __syncthreads();

        int toff = (tap / 3) * IN_W + (tap - (tap / 3) * 3);
        const __nv_bfloat16* A0 = Xh + (mt * 16 + toff) * LDX;
        const __nv_bfloat16* A1 = Xl + (mt * 16 + toff) * LDX;
        #pragma unroll
        for (int k = 0; k < 4; ++k) {
            wmma::fragment<wmma::matrix_a, 16, 16, 16, __nv_bfloat16, wmma::row_major> ah, al;
            wmma::load_matrix_sync(ah, A0 + k * 16, LDX);
            wmma::load_matrix_sync(al, A1 + k * 16, LDX);
            #pragma unroll
            for (int nt = 0; nt < 2; ++nt) {
                wmma::fragment<wmma::matrix_b, 16, 16, 16, __nv_bfloat16, wmma::row_major> bh, bl;
                wmma::load_matrix_sync(bh, Wh + k * 16 * LDX + nh * 32 + nt * 16, LDX);
                wmma::load_matrix_sync(bl, Wl + k * 16 * LDX + nh * 32 + nt * 16, LDX);
                wmma::mma_sync(acc[nt], ah, bh, acc[nt]);
                wmma::mma_sync(acc[nt], ah, bl, acc[nt]);
                wmma::mma_sync(acc[nt], al, bh, acc[nt]);
            }
        }
    }

    __syncthreads();
    float* patch = (float*)(smc + OPATCH) + wid * 16 * 36;
    float* x3s = (float*)(smc + OX3);
    float* xout = FUSE4 ? nullptr : (xout_base + (size_t)b * OUT_W * OUT_W * 64);
    if (FUSE4)
        for (int i = tid; i < 576; i += TPB) ws4[i] = w4[i];

    {
        wmma::store_matrix_sync(patch,      acc[0], 36, wmma::mem_row_major);
        wmma::store_matrix_sync(patch + 16, acc[1], 36, wmma::mem_row_major);
        __syncwarp();
        int r = lane & 15, ch = (lane >> 4) * 16;
        int p = mt * 16 + r;
        int y = p / IN_W, x = p - y * IN_W;
        if (y < OUT_W && x < OUT_W) {
            int orow = y * OUT_W + x;
            #pragma unroll
            for (int j = 0; j < 16; ++j) {
                int c = nh * 32 + ch + j;
                float v = fmaxf(sbs[c] * patch[r * 36 + ch + j] + sbs[64 + c], 0.f);
                if (FUSE4) x3s[orow * 68 + c] = v;
                else       xout[orow * 64 + c] = v;
            }
        }
    }

    if (FUSE4) {
        __syncthreads();
        float lm = -INFINITY;
        if (tid < 81) {
            int y = tid / 9, x = tid - (tid / 9) * 9;
            float a = 0.f;
            #pragma unroll
            for (int ky = 0; ky < 3; ++ky)
                #pragma unroll
                for (int kx = 0; kx < 3; ++kx) {
                    const float* row = x3s + ((y + ky) * OUT_W + (x + kx)) * 68;
                    int t = ky * 3 + kx;
                    for (int ic = 0; ic < 64; ++ic)
                        a += row[ic] * ws4[ic * 9 + t];
                }
            lm = a;
        }
        #pragma unroll
        for (int off = 16; off > 0; off >>= 1) lm = fmaxf(lm, __shfl_xor_sync(0xffffffffu, lm, off));
        if (lane == 0) red[wid] = lm;
        __syncthreads();
        if (tid == 0) {
            float v = -INFINITY;
            for (int i = 0; i < TPB / 32; ++i) v = fmaxf(v, red[i]);
            out[b] = v + cb4[0];
        }
    }
}

// ---------------------------------------------------------------------------
extern "C" void kernel_launch(void* const* d_in, const int* in_sizes, int n_in,
                              void* d_out, int out_size)
{
    // conv2: XROWS=240 -> OX3 not used; smem = OPATCH + 26*2304 = 88064+59904 = 147968
    // conv3: XROWS=176 -> OPATCH=69632, +18*2304=41472 -> OX3=111104, +121*68*4=32912 -> 144016
    const int S2 = 147968;
    const int S3 = 144032;
    static float *p1 = nullptr, *p2 = nullptr;
    if (!p1) {
        cudaGetSymbolAddress((void**)&p1, g_x1);
        cudaGetSymbolAddress((void**)&p2, g_x2);
        cudaFuncSetAttribute(convmma_kernel<15,13,false,832>, cudaFuncAttributeMaxDynamicSharedMemorySize, S2);
        cudaFuncSetAttribute(convmma_kernel<13,11,true,576>,  cudaFuncAttributeMaxDynamicSharedMemorySize, S3);
    }

    wprep_kernel<<<288, 256>>>((const float*)d_in[11], (const float*)d_in[17]);

    stats_kernel<<<BTOT, 1024>>>(
        (const float*)d_in[0], (const float*)d_in[1],
        (const float*)d_in[2], (const float*)d_in[3], d_in[4]);

    conv1_kernel<<<BTOT, TPB1>>>(
        (const float*)d_in[5],  (const float*)d_in[6],
        (const float*)d_in[7],  (const float*)d_in[8],
        (const float*)d_in[9],  (const float*)d_in[10]);

    convmma_kernel<15,13,false,832><<<BTOT, 832, S2>>>(
        p1, p2, 0,
        (const float*)d_in[12],
        (const float*)d_in[13], (const float*)d_in[14],
        (const float*)d_in[15], (const float*)d_in[16],
        nullptr, nullptr, nullptr);

    convmma_kernel<13,11,true,576><<<BTOT, 576, S3>>>(
        p2, nullptr, 36864,
        (const float*)d_in[18],
        (const float*)d_in[19], (const float*)d_in[20],
        (const float*)d_in[21], (const float*)d_in[22],
        (const float*)d_in[23], (const float*)d_in[24],
        (float*)d_out);
}

// round 12
// speedup vs baseline: 1.0631x; 1.0297x over previous
#include <cuda_runtime.h>
#include <cuda_bf16.h>
#include <mma.h>
#include <math.h>
#include <stdint.h>

using namespace nvcuda;

#define BTOT 512
#define NMEM 30
#define HW 1024
#define NGTH_ 15

typedef unsigned long long u64;

__device__ __forceinline__ u64 dup2f(float v){u64 r;asm("mov.b64 %0,{%1,%1};":"=l"(r):"f"(v));return r;}
__device__ __forceinline__ void fma2(u64&d,u64 a,u64 b){asm("fma.rn.f32x2 %0,%1,%2,%0;":"+l"(d):"l"(a),"l"(b));}
__device__ __forceinline__ float2 unp2(u64 v){float lo,hi;asm("mov.b64 {%0,%1},%2;":"=f"(lo),"=f"(hi):"l"(v));return make_float2(lo,hi);}

__device__ float g_inp6[(size_t)BTOT*6*HW];
__device__ float g_cst[(size_t)BTOT*8];
__device__ float g_x1[(size_t)BTOT*225*64];   // pos-major [p][oc]
__device__ float g_x2[(size_t)BTOT*169*64];
__device__ __nv_bfloat16 g_wh[2*9*4096];      // [conv][tap][ic][oc] hi
__device__ __nv_bfloat16 g_wl[2*9*4096];      // lo

// ---------------------------------------------------------------------------
// Kernel 0: weight prep — w2/w3 -> bf16 hi/lo, tap-major coalesced layout
// ---------------------------------------------------------------------------
__global__ __launch_bounds__(256) void wprep_kernel(
    const float* __restrict__ w2, const float* __restrict__ w3)
{
    int i = blockIdx.x * 256 + threadIdx.x;
    if (i < 2 * 9 * 4096) {
        int conv = i / 36864, r = i - conv * 36864;
        int tap = r >> 12, idx = r & 4095;
        int ic = idx >> 6, oc = idx & 63;
        const float* w = conv ? w3 : w2;
        float v = w[oc * 576 + ic * 9 + tap];
        __nv_bfloat16 h = __float2bfloat16(v);
        g_wh[i] = h;
        g_wl[i] = __float2bfloat16(v - __bfloat162float(h));
    }
}

// ---------------------------------------------------------------------------
// Kernel 1: stats — 1024 threads (1/pixel), high-MLP
// ---------------------------------------------------------------------------
__global__ __launch_bounds__(1024) void stats_kernel(
    const float* __restrict__ ts, const float* __restrict__ ptm,
    const float* __restrict__ pmt, const float* __restrict__ piou,
    const void* __restrict__ mask_raw)
{
    const int b = blockIdx.x, tid = threadIdx.x, lane = tid & 31, wid = tid >> 5;
    __shared__ float mf[NMEM], ow[NMEM], pmax[NMEM], warpmax[32], sc[16];

    unsigned int w0 = *(const unsigned int*)mask_raw;
    int mode = (w0 == 1u) ? 1 : ((w0 == 0x3F800000u) ? 2 : 0);

    if (tid == 0) {
        float run = 0.f, ca = 0.f, cg = 0.f, co = 0.f;
        for (int m = 0; m < NMEM; ++m) {
            int idx = b * NMEM + m; float f;
            if (mode == 1)      f = (((const int*)mask_raw)[idx] != 0) ? 1.f : 0.f;
            else if (mode == 2) f = (((const float*)mask_raw)[idx] != 0.f) ? 1.f : 0.f;
            else                f = (((const unsigned char*)mask_raw)[idx] != 0) ? 1.f : 0.f;
            run += f;
            float g = (run - 1.f < (float)NGTH_) ? f : 0.f;
            float o = f - g;
            mf[m] = f; ow[m] = o; ca += f; cg += g; co += o;
        }
        sc[7] = ca; sc[8] = cg; sc[9] = co;
    }

    {
        float v = ts[(size_t)b * HW + tid];
        #pragma unroll
        for (int off = 16; off > 0; off >>= 1) v = fmaxf(v, __shfl_xor_sync(0xffffffffu, v, off));
        if (lane == 0) warpmax[wid] = v;
    }

    if (wid < NMEM) {
        const float* pr = ptm + (size_t)b * NMEM * HW + (size_t)wid * HW;
        float mx = -INFINITY;
        #pragma unroll
        for (int k = 0; k < 32; ++k) mx = fmaxf(mx, pr[lane + 32 * k]);
        #pragma unroll
        for (int off = 16; off > 0; off >>= 1) mx = fmaxf(mx, __shfl_xor_sync(0xffffffffu, mx, off));
        if (lane == 0) pmax[wid] = mx;
    }
    __syncthreads();

    if (wid == 0) {
        float v = warpmax[lane];
        #pragma unroll
        for (int off = 16; off > 0; off >>= 1) v = fmaxf(v, __shfl_xor_sync(0xffffffffu, v, off));
        if (lane == 0) sc[0] = v;
    }
    if (wid == 1) {
        float v  = (lane < NMEM) ? pmax[lane] : 0.f;
        float fa = (lane < NMEM) ? mf[lane] : 0.f;
        float fo = (lane < NMEM) ? ow[lane] : 0.f;
        float fg = fa - fo;
        float sa = v*fa, ssa = v*v*fa, sg = v*fg, ssg = v*v*fg, so = v*fo, sso = v*v*fo;
        #pragma unroll
        for (int off = 16; off > 0; off >>= 1) {
            sa  += __shfl_xor_sync(0xffffffffu, sa, off);  ssa += __shfl_xor_sync(0xffffffffu, ssa, off);
            sg  += __shfl_xor_sync(0xffffffffu, sg, off);  ssg += __shfl_xor_sync(0xffffffffu, ssg, off);
            so  += __shfl_xor_sync(0xffffffffu, so, off);  sso += __shfl_xor_sync(0xffffffffu, sso, off);
        }
        if (lane == 0) {
            float ca = sc[7], cg = sc[8], co = sc[9];
            float mA = sa / ca; sc[1] = mA; sc[2] = sqrtf(fmaxf(ssa / ca - mA * mA, 0.f));
            float mG = sg / cg; sc[3] = mG; sc[4] = sqrtf(fmaxf(ssg / cg - mG * mG, 0.f));
            float mO = so / co; sc[5] = mO; sc[6] = sqrtf(fmaxf(sso / co - mO * mO, 0.f));
        }
    }
    __syncthreads();

    if (tid == 0) {
        float* c = g_cst + (size_t)b * 8;
        c[0] = sc[0]; c[1] = piou[b]; c[2] = sc[1]; c[3] = sc[2];
        c[4] = sc[3]; c[5] = sc[4];   c[6] = sc[5]; c[7] = sc[6];
    }

    {
        const float* pmtb = pmt + (size_t)b * NMEM * HW + tid;
        const float ca = sc[7], co = sc[9];
        float sa = 0, ssa = 0, sg = 0, ssg = 0, so = 0, sso = 0;
        #pragma unroll
        for (int m = 0; m < NMEM; ++m) {
            float v = pmtb[(size_t)m * HW];
            float fa = mf[m], fo = ow[m];
            sa += v * fa; ssa += v * v * fa;
            if (m < NGTH_) { sg += v; ssg += v * v; }
            so += v * fo; sso += v * v * fo;
        }
        float mA = sa / ca, sA = sqrtf(fmaxf(ssa / ca - mA * mA, 0.f));
        float mG = sg * (1.f / NGTH_), sG = sqrtf(fmaxf(ssg * (1.f / NGTH_) - mG * mG, 0.f));
        float mO = so / co, sO = sqrtf(fmaxf(sso / co - mO * mO, 0.f));
        float* ob = g_inp6 + (size_t)b * 6 * HW + tid;
        ob[0*HW] = mA; ob[1*HW] = sA; ob[2*HW] = mG;
        ob[3*HW] = sG; ob[4*HW] = mO; ob[5*HW] = sO;
    }
}

// ---------------------------------------------------------------------------
// Kernel 2: conv1 + bn + relu + pool -> g_x1 pos-major (validated R9)
// ---------------------------------------------------------------------------
#define TPB1 480
__global__ __launch_bounds__(TPB1, 1) void conv1_kernel(
    const float* __restrict__ w1, const float* __restrict__ cb1,
    const float* __restrict__ g1, const float* __restrict__ bb1,
    const float* __restrict__ m1, const float* __restrict__ v1)
{
    __shared__ float sm[6528 + 3456 + 128];
    const int IW_ = 6528, IE_ = 9984;
    const int b = blockIdx.x, tid = threadIdx.x;

    {
        const float* src = g_inp6 + (size_t)b * 6 * HW;
        for (int i = tid; i < 6 * HW; i += TPB1) {
            int c = i >> 10; int rem = i & 1023;
            sm[c * 1088 + (rem >> 5) * 34 + (rem & 31)] = src[i];
        }
        for (int i = tid; i < 64 * 6 * 9; i += TPB1) {
            int oc = i / 54; int r = i - oc * 54;
            int c = r / 9; int t = r - c * 9;
            sm[IW_ + ((oc >> 1) * 6 + c) * 18 + t * 2 + (oc & 1)] = w1[oc * 126 + (c + 2) * 9 + t];
        }
        if (tid < 64) {
            const float* cst = g_cst + (size_t)b * 8;
            float extra = 0.f;
            #pragma unroll
            for (int j = 0; j < 8; ++j) {
                int ic = (j < 2) ? j : (j + 6);
                const float* wb = w1 + tid * 126 + ic * 9;
                float s9 = 0.f;
                #pragma unroll
                for (int t = 0; t < 9; ++t) s9 += wb[t];
                extra += cst[j] * s9;
            }
            float s = g1[tid] * rsqrtf(v1[tid] + 1e-5f);
            sm[IE_ + tid] = s;
            sm[IE_ + 64 + tid] = s * (extra + cb1[tid] - m1[tid]) + bb1[tid];
        }
    }
    __syncthreads();

    float* xo = g_x1 + (size_t)b * 225 * 64;
    #pragma unroll
    for (int itb = 0; itb < 2; ++itb) {
        int it = tid + itb * TPB1;
        int ocg = it / 60;
        int r = it - ocg * 60;
        int pr = r >> 2, pq = r & 3;
        int x0 = 8 * pq, r0 = 2 * pr;

        u64 acc[2][2][8];
        #pragma unroll
        for (int p = 0; p < 2; ++p)
            #pragma unroll
            for (int e = 0; e < 2; ++e)
                #pragma unroll
                for (int c = 0; c < 8; ++c) acc[p][e][c] = 0ull;

        for (int ch = 0; ch < 6; ++ch) {
            const float* ib = &sm[ch * 1088 + r0 * 34 + x0];
            const u64* wb0 = (const u64*)&sm[IW_ + ((ocg * 2) * 6 + ch) * 18];
            const u64* wb1 = (const u64*)&sm[IW_ + ((ocg * 2 + 1) * 6 + ch) * 18];
            #pragma unroll
            for (int ir = 0; ir < 4; ++ir) {
                u64 d[10];
                #pragma unroll
                for (int q = 0; q < 5; ++q) {
                    float2 a = *(const float2*)(ib + ir * 34 + 2 * q);
                    d[2*q] = dup2f(a.x); d[2*q+1] = dup2f(a.y);
                }
                #pragma unroll
                for (int kx = 0; kx < 3; ++kx) {
                    if (ir <= 2) {
                        u64 wa = wb0[ir*3+kx], wc = wb1[ir*3+kx];
                        #pragma unroll
                        for (int c = 0; c < 8; ++c) { fma2(acc[0][0][c], wa, d[c+kx]); fma2(acc[1][0][c], wc, d[c+kx]); }
                    }
                    if (ir >= 1) {
                        u64 wa = wb0[(ir-1)*3+kx], wc = wb1[(ir-1)*3+kx];
                        #pragma unroll
                        for (int c = 0; c < 8; ++c) { fma2(acc[0][1][c], wa, d[c+kx]); fma2(acc[1][1][c], wc, d[c+kx]); }
                    }
                }
            }
        }
        #pragma unroll
        for (int p = 0; p < 2; ++p) {
            int oc0 = ocg * 4 + 2 * p;
            float s0 = sm[IE_+oc0], bi0 = sm[IE_+64+oc0];
            float s1 = sm[IE_+oc0+1], bi1 = sm[IE_+64+oc0+1];
            #pragma unroll
            for (int j = 0; j < 4; ++j) {
                int pt = 4 * pq + j;
                if (pt < 15) {
                    float2 a = unp2(acc[p][0][2*j]), bq = unp2(acc[p][0][2*j+1]);
                    float2 cq = unp2(acc[p][1][2*j]), e = unp2(acc[p][1][2*j+1]);
                    float lo = fmaxf(fmaxf(fmaxf(s0*a.x+bi0,0.f), fmaxf(s0*bq.x+bi0,0.f)),
                                     fmaxf(fmaxf(s0*cq.x+bi0,0.f), fmaxf(s0*e.x+bi0,0.f)));
                    float hi = fmaxf(fmaxf(fmaxf(s1*a.y+bi1,0.f), fmaxf(s1*bq.y+bi1,0.f)),
                                     fmaxf(fmaxf(s1*cq.y+bi1,0.f), fmaxf(s1*e.y+bi1,0.f)));
                    int pos = pr * 15 + pt;
                    xo[pos * 64 + oc0] = lo;
                    xo[pos * 64 + oc0 + 1] = hi;
                }
            }
        }
    }
}

// ---------------------------------------------------------------------------
// Kernel 3/4: conv 64->64, 9 tap-GEMMs, bf16 wmma 3-pass.
// All 9 taps of W resident in smem per split-half (hi then lo):
// mainloop barriers 18 -> 3. Four independent acc chains (P[2], Q[2]).
// FUSE4: conv4 + global max in-kernel.
// ---------------------------------------------------------------------------
template<int IN_W, int OUT_W, bool FUSE4, int TPB>
__global__ __launch_bounds__(TPB, 1) void convmma_kernel(
    const float* __restrict__ xin_base, float* __restrict__ xout_base,
    int woff,
    const float* __restrict__ cb,
    const float* __restrict__ gg, const float* __restrict__ bbv,
    const float* __restrict__ mmv, const float* __restrict__ vvv,
    const float* __restrict__ w4, const float* __restrict__ cb4,
    float* __restrict__ out)
{
    constexpr int INROWS = IN_W * IN_W;
    constexpr int MMAX = (OUT_W - 1) * IN_W + OUT_W;
    constexpr int MTILES = (MMAX + 15) / 16;
    constexpr int XROWS = ((MTILES * 16 + 2 * IN_W + 2 + 15) / 16) * 16;
    constexpr int NUNITS = MTILES * 2;       // == TPB/32
    constexpr int LDX = 72, LDW = 72;
    constexpr int OXH = 0;
    constexpr int OXL = OXH + XROWS * LDX * 2;
    constexpr int OW  = OXL + XROWS * LDX * 2;
    constexpr int OSB = OW + 9 * 64 * LDW * 2;     // W buffer: 82944 B
    constexpr int OPATCH = OW;                      // alias (post-mainloop)
    constexpr int OX3 = OW + NUNITS * 16 * 36 * 4;  // alias after patch

    extern __shared__ char smc[];
    __nv_bfloat16* Xh = (__nv_bfloat16*)(smc + OXH);
    __nv_bfloat16* Xl = (__nv_bfloat16*)(smc + OXL);
    __nv_bfloat16* Wsm = (__nv_bfloat16*)(smc + OW);
    float* sbs = (float*)(smc + OSB);
    __shared__ float ws4[576];
    __shared__ float red[32];

    const int b = blockIdx.x, tid = threadIdx.x, wid = tid >> 5, lane = tid & 31;
    const float* xin = xin_base + (size_t)b * INROWS * 64;

    // X hi/lo into smem
    for (int i = tid; i < INROWS * 64; i += TPB) {
        int p = i >> 6, c = i & 63;
        float v = xin[i];
        __nv_bfloat16 h = __float2bfloat16(v);
        Xh[p * LDX + c] = h;
        Xl[p * LDX + c] = __float2bfloat16(v - __bfloat162float(h));
    }
    for (int i = tid; i < (XROWS - INROWS) * 64; i += TPB) {
        int p = INROWS + (i >> 6), c = i & 63;
        Xh[p * LDX + c] = __float2bfloat16(0.f);
        Xl[p * LDX + c] = __float2bfloat16(0.f);
    }
    if (tid < 64) {
        float s = gg[tid] * rsqrtf(vvv[tid] + 1e-5f);
        sbs[tid] = s;
        sbs[64 + tid] = s * (cb[tid] - mmv[tid]) + bbv[tid];
    }
    // W hi (all 9 taps)
    {
        const __nv_bfloat16* sh = g_wh + woff;
        for (int i = tid; i < 9 * 4096; i += TPB) {
            int ti = i >> 12, idx = i & 4095;
            int ic = idx >> 6, oc = idx & 63;
            Wsm[(ti * 64 + ic) * LDW + oc] = sh[i];
        }
    }
    __syncthreads();

    const int mt = wid >> 1, nh = wid & 1;

    wmma::fragment<wmma::accumulator, 16, 16, 16, float> P[2], Q[2];
    wmma::fill_fragment(P[0], 0.f); wmma::fill_fragment(P[1], 0.f);
    wmma::fill_fragment(Q[0], 0.f); wmma::fill_fragment(Q[1], 0.f);

    // ---- phase A: ah*bh -> P, al*bh -> Q ----
    #pragma unroll 1
    for (int tap = 0; tap < 9; ++tap) {
        int toff = (tap / 3) * IN_W + (tap - (tap / 3) * 3);
        const __nv_bfloat16* A0 = Xh + (mt * 16 + toff) * LDX;
        const __nv_bfloat16* A1 = Xl + (mt * 16 + toff) * LDX;
        const __nv_bfloat16* B = Wsm + (tap * 64) * LDW + nh * 32;
        #pragma unroll
        for (int k = 0; k < 4; ++k) {
            wmma::fragment<wmma::matrix_a, 16, 16, 16, __nv_bfloat16, wmma::row_major> ah, al;
            wmma::load_matrix_sync(ah, A0 + k * 16, LDX);
            wmma::load_matrix_sync(al, A1 + k * 16, LDX);
            #pragma unroll
            for (int nt = 0; nt < 2; ++nt) {
                wmma::fragment<wmma::matrix_b, 16, 16, 16, __nv_bfloat16, wmma::row_major> bh;
                wmma::load_matrix_sync(bh, B + k * 16 * LDW + nt * 16, LDW);
                wmma::mma_sync(P[nt], ah, bh, P[nt]);
                wmma::mma_sync(Q[nt], al, bh, Q[nt]);
            }
        }
    }

    // ---- swap W buffer to lo ----
    __syncthreads();
    {
        const __nv_bfloat16* sl = g_wl + woff;
        for (int i = tid; i < 9 * 4096; i += TPB) {
            int ti = i >> 12, idx = i & 4095;
            int ic = idx >> 6, oc = idx & 63;
            Wsm[(ti * 64 + ic) * LDW + oc] = sl[i];
        }
    }
    __syncthreads();

    // ---- phase B: ah*bl -> Q ----
    #pragma unroll 1
    for (int tap = 0; tap < 9; ++tap) {
        int toff = (tap / 3) * IN_W + (tap - (tap / 3) * 3);
        const __nv_bfloat16* A0 = Xh + (mt * 16 + toff) * LDX;
        const __nv_bfloat16* B = Wsm + (tap * 64) * LDW + nh * 32;
        #pragma unroll
        for (int k = 0; k < 4; ++k) {
            wmma::fragment<wmma::matrix_a, 16, 16, 16, __nv_bfloat16, wmma::row_major> ah;
            wmma::load_matrix_sync(ah, A0 + k * 16, LDX);
            #pragma unroll
            for (int nt = 0; nt < 2; ++nt) {
                wmma::fragment<wmma::matrix_b, 16, 16, 16, __nv_bfloat16, wmma::row_major> bl;
                wmma::load_matrix_sync(bl, B + k * 16 * LDW + nt * 16, LDW);
                wmma::mma_sync(Q[nt], ah, bl, Q[nt]);
            }
        }
    }

    // ---- merge chains ----
    #pragma unroll
    for (int nt = 0; nt < 2; ++nt)
        #pragma unroll
        for (int i = 0; i < P[nt].num_elements; ++i)
            P[nt].x[i] += Q[nt].x[i];

    // ---- epilogue (patch/x3s alias W region) ----
    __syncthreads();
    float* patch = (float*)(smc + OPATCH) + wid * 16 * 36;
    float* x3s = (float*)(smc + OX3);
    float* xout = FUSE4 ? nullptr : (xout_base + (size_t)b * OUT_W * OUT_W * 64);
    if (FUSE4)
        for (int i = tid; i < 576; i += TPB) ws4[i] = w4[i];

    {
        wmma::store_matrix_sync(patch,      P[0], 36, wmma::mem_row_major);
        wmma::store_matrix_sync(patch + 16, P[1], 36, wmma::mem_row_major);
        __syncwarp();
        int r = lane & 15, ch = (lane >> 4) * 16;
        int p = mt * 16 + r;
        int y = p / IN_W, x = p - y * IN_W;
        if (y < OUT_W && x < OUT_W) {
            int orow = y * OUT_W + x;
            #pragma unroll
            for (int j = 0; j < 16; ++j) {
                int c = nh * 32 + ch + j;
                float v = fmaxf(sbs[c] * patch[r * 36 + ch + j] + sbs[64 + c], 0.f);
                if (FUSE4) x3s[orow * 68 + c] = v;
                else       xout[orow * 64 + c] = v;
            }
        }
    }

    if (FUSE4) {
        __syncthreads();
        float lm = -INFINITY;
        if (tid < 81) {
            int y = tid / 9, x = tid - (tid / 9) * 9;
            float a = 0.f;
            #pragma unroll
            for (int ky = 0; ky < 3; ++ky)
                #pragma unroll
                for (int kx = 0; kx < 3; ++kx) {
                    const float* row = x3s + ((y + ky) * OUT_W + (x + kx)) * 68;
                    int t = ky * 3 + kx;
                    for (int ic = 0; ic < 64; ++ic)
                        a += row[ic] * ws4[ic * 9 + t];
                }
            lm = a;
        }
        #pragma unroll
        for (int off = 16; off > 0; off >>= 1) lm = fmaxf(lm, __shfl_xor_sync(0xffffffffu, lm, off));
        if (lane == 0) red[wid] = lm;
        __syncthreads();
        if (tid == 0) {
            float v = -INFINITY;
            for (int i = 0; i < TPB / 32; ++i) v = fmaxf(v, red[i]);
            out[b] = v + cb4[0];
        }
    }
}

// ---------------------------------------------------------------------------
extern "C" void kernel_launch(void* const* d_in, const int* in_sizes, int n_in,
                              void* d_out, int out_size)
{
    // conv2: X 69120 + W 82944 + sbs 512 = 152576
    // conv3: X 50688 + W 82944 + sbs 512 = 134144
    //        (x3s alias at OW+41472, needs 32912 <= 41472 OK)
    const int S2 = 152576;
    const int S3 = 134144;
    static float *p1 = nullptr, *p2 = nullptr;
    if (!p1) {
        cudaGetSymbolAddress((void**)&p1, g_x1);
        cudaGetSymbolAddress((void**)&p2, g_x2);
        cudaFuncSetAttribute(convmma_kernel<15,13,false,832>, cudaFuncAttributeMaxDynamicSharedMemorySize, S2);
        cudaFuncSetAttribute(convmma_kernel<13,11,true,576>,  cudaFuncAttributeMaxDynamicSharedMemorySize, S3);
    }

    wprep_kernel<<<288, 256>>>((const float*)d_in[11], (const float*)d_in[17]);

    stats_kernel<<<BTOT, 1024>>>(
        (const float*)d_in[0], (const float*)d_in[1],
        (const float*)d_in[2], (const float*)d_in[3], d_in[4]);

    conv1_kernel<<<BTOT, TPB1>>>(
        (const float*)d_in[5],  (const float*)d_in[6],
        (const float*)d_in[7],  (const float*)d_in[8],
        (const float*)d_in[9],  (const float*)d_in[10]);

    convmma_kernel<15,13,false,832><<<BTOT, 832, S2>>>(
        p1, p2, 0,
        (const float*)d_in[12],
        (const float*)d_in[13], (const float*)d_in[14],
        (const float*)d_in[15], (const float*)d_in[16],
        nullptr, nullptr, nullptr);

    convmma_kernel<13,11,true,576><<<BTOT, 576, S3>>>(
        p2, nullptr, 36864,
        (const float*)d_in[18],
        (const float*)d_in[19], (const float*)d_in[20],
        (const float*)d_in[21], (const float*)d_in[22],
        (const float*)d_in[23], (const float*)d_in[24],
        (float*)d_out);
}

// round 13
// speedup vs baseline: 1.2750x; 1.1993x over previous
#include <cuda_runtime.h>
#include <cuda_bf16.h>
#include <mma.h>
#include <math.h>
#include <stdint.h>

using namespace nvcuda;

#define BTOT 512
#define NMEM 30
#define HW 1024
#define NGTH_ 15

typedef unsigned long long u64;

__device__ __forceinline__ u64 dup2f(float v){u64 r;asm("mov.b64 %0,{%1,%1};":"=l"(r):"f"(v));return r;}
__device__ __forceinline__ void fma2(u64&d,u64 a,u64 b){asm("fma.rn.f32x2 %0,%1,%2,%0;":"+l"(d):"l"(a),"l"(b));}
__device__ __forceinline__ float2 unp2(u64 v){float lo,hi;asm("mov.b64 {%0,%1},%2;":"=f"(lo),"=f"(hi):"l"(v));return make_float2(lo,hi);}

__device__ float g_inp6[(size_t)BTOT*6*HW];
__device__ float g_cst[(size_t)BTOT*8];
__device__ __nv_bfloat16 g_x1h[(size_t)BTOT*225*64];
__device__ __nv_bfloat16 g_x1l[(size_t)BTOT*225*64];
__device__ __nv_bfloat16 g_x2h[(size_t)BTOT*169*64];
__device__ __nv_bfloat16 g_x2l[(size_t)BTOT*169*64];
__device__ __nv_bfloat16 g_wh[2*9*4096];      // [conv][tap][ic][oc] hi
__device__ __nv_bfloat16 g_wl[2*9*4096];      // lo

__device__ __forceinline__ unsigned pack2bf(float a, float b) {
    return (unsigned)__bfloat16_as_ushort(__float2bfloat16(a)) |
           ((unsigned)__bfloat16_as_ushort(__float2bfloat16(b)) << 16);
}

// ---------------------------------------------------------------------------
// Kernel 0: weight prep — w2/w3 -> bf16 hi/lo, tap-major coalesced layout
// ---------------------------------------------------------------------------
__global__ __launch_bounds__(256) void wprep_kernel(
    const float* __restrict__ w2, const float* __restrict__ w3)
{
    int i = blockIdx.x * 256 + threadIdx.x;
    if (i < 2 * 9 * 4096) {
        int conv = i / 36864, r = i - conv * 36864;
        int tap = r >> 12, idx = r & 4095;
        int ic = idx >> 6, oc = idx & 63;
        const float* w = conv ? w3 : w2;
        float v = w[oc * 576 + ic * 9 + tap];
        __nv_bfloat16 h = __float2bfloat16(v);
        g_wh[i] = h;
        g_wl[i] = __float2bfloat16(v - __bfloat162float(h));
    }
}

// ---------------------------------------------------------------------------
// Kernel 1: stats — 1024 threads (1/pixel), high-MLP  (validated R11)
// ---------------------------------------------------------------------------
__global__ __launch_bounds__(1024) void stats_kernel(
    const float* __restrict__ ts, const float* __restrict__ ptm,
    const float* __restrict__ pmt, const float* __restrict__ piou,
    const void* __restrict__ mask_raw)
{
    const int b = blockIdx.x, tid = threadIdx.x, lane = tid & 31, wid = tid >> 5;
    __shared__ float mf[NMEM], ow[NMEM], pmax[NMEM], warpmax[32], sc[16];

    unsigned int w0 = *(const unsigned int*)mask_raw;
    int mode = (w0 == 1u) ? 1 : ((w0 == 0x3F800000u) ? 2 : 0);

    if (tid == 0) {
        float run = 0.f, ca = 0.f, cg = 0.f, co = 0.f;
        for (int m = 0; m < NMEM; ++m) {
            int idx = b * NMEM + m; float f;
            if (mode == 1)      f = (((const int*)mask_raw)[idx] != 0) ? 1.f : 0.f;
            else if (mode == 2) f = (((const float*)mask_raw)[idx] != 0.f) ? 1.f : 0.f;
            else                f = (((const unsigned char*)mask_raw)[idx] != 0) ? 1.f : 0.f;
            run += f;
            float g = (run - 1.f < (float)NGTH_) ? f : 0.f;
            float o = f - g;
            mf[m] = f; ow[m] = o; ca += f; cg += g; co += o;
        }
        sc[7] = ca; sc[8] = cg; sc[9] = co;
    }

    {
        float v = ts[(size_t)b * HW + tid];
        #pragma unroll
        for (int off = 16; off > 0; off >>= 1) v = fmaxf(v, __shfl_xor_sync(0xffffffffu, v, off));
        if (lane == 0) warpmax[wid] = v;
    }

    if (wid < NMEM) {
        const float* pr = ptm + (size_t)b * NMEM * HW + (size_t)wid * HW;
        float mx = -INFINITY;
        #pragma unroll
        for (int k = 0; k < 32; ++k) mx = fmaxf(mx, pr[lane + 32 * k]);
        #pragma unroll
        for (int off = 16; off > 0; off >>= 1) mx = fmaxf(mx, __shfl_xor_sync(0xffffffffu, mx, off));
        if (lane == 0) pmax[wid] = mx;
    }
    __syncthreads();

    if (wid == 0) {
        float v = warpmax[lane];
        #pragma unroll
        for (int off = 16; off > 0; off >>= 1) v = fmaxf(v, __shfl_xor_sync(0xffffffffu, v, off));
        if (lane == 0) sc[0] = v;
    }
    if (wid == 1) {
        float v  = (lane < NMEM) ? pmax[lane] : 0.f;
        float fa = (lane < NMEM) ? mf[lane] : 0.f;
        float fo = (lane < NMEM) ? ow[lane] : 0.f;
        float fg = fa - fo;
        float sa = v*fa, ssa = v*v*fa, sg = v*fg, ssg = v*v*fg, so = v*fo, sso = v*v*fo;
        #pragma unroll
        for (int off = 16; off > 0; off >>= 1) {
            sa  += __shfl_xor_sync(0xffffffffu, sa, off);  ssa += __shfl_xor_sync(0xffffffffu, ssa, off);
            sg  += __shfl_xor_sync(0xffffffffu, sg, off);  ssg += __shfl_xor_sync(0xffffffffu, ssg, off);
            so  += __shfl_xor_sync(0xffffffffu, so, off);  sso += __shfl_xor_sync(0xffffffffu, sso, off);
        }
        if (lane == 0) {
            float ca = sc[7], cg = sc[8], co = sc[9];
            float mA = sa / ca; sc[1] = mA; sc[2] = sqrtf(fmaxf(ssa / ca - mA * mA, 0.f));
            float mG = sg / cg; sc[3] = mG; sc[4] = sqrtf(fmaxf(ssg / cg - mG * mG, 0.f));
            float mO = so / co; sc[5] = mO; sc[6] = sqrtf(fmaxf(sso / co - mO * mO, 0.f));
        }
    }
    __syncthreads();

    if (tid == 0) {
        float* c = g_cst + (size_t)b * 8;
        c[0] = sc[0]; c[1] = piou[b]; c[2] = sc[1]; c[3] = sc[2];
        c[4] = sc[3]; c[5] = sc[4];   c[6] = sc[5]; c[7] = sc[6];
    }

    {
        const float* pmtb = pmt + (size_t)b * NMEM * HW + tid;
        const float ca = sc[7], co = sc[9];
        float sa = 0, ssa = 0, sg = 0, ssg = 0, so = 0, sso = 0;
        #pragma unroll
        for (int m = 0; m < NMEM; ++m) {
            float v = pmtb[(size_t)m * HW];
            float fa = mf[m], fo = ow[m];
            sa += v * fa; ssa += v * v * fa;
            if (m < NGTH_) { sg += v; ssg += v * v; }
            so += v * fo; sso += v * v * fo;
        }
        float mA = sa / ca, sA = sqrtf(fmaxf(ssa / ca - mA * mA, 0.f));
        float mG = sg * (1.f / NGTH_), sG = sqrtf(fmaxf(ssg * (1.f / NGTH_) - mG * mG, 0.f));
        float mO = so / co, sO = sqrtf(fmaxf(sso / co - mO * mO, 0.f));
        float* ob = g_inp6 + (size_t)b * 6 * HW + tid;
        ob[0*HW] = mA; ob[1*HW] = sA; ob[2*HW] = mG;
        ob[3*HW] = sG; ob[4*HW] = mO; ob[5*HW] = sO;
    }
}

// ---------------------------------------------------------------------------
// Kernel 2: conv1 + bn + relu + pool -> g_x1h/g_x1l pos-major (bf16 hi/lo)
// ---------------------------------------------------------------------------
#define TPB1 480
__global__ __launch_bounds__(TPB1, 1) void conv1_kernel(
    const float* __restrict__ w1, const float* __restrict__ cb1,
    const float* __restrict__ g1, const float* __restrict__ bb1,
    const float* __restrict__ m1, const float* __restrict__ v1)
{
    __shared__ float sm[6528 + 3456 + 128];
    const int IW_ = 6528, IE_ = 9984;
    const int b = blockIdx.x, tid = threadIdx.x;

    {
        const float* src = g_inp6 + (size_t)b * 6 * HW;
        for (int i = tid; i < 6 * HW; i += TPB1) {
            int c = i >> 10; int rem = i & 1023;
            sm[c * 1088 + (rem >> 5) * 34 + (rem & 31)] = src[i];
        }
        for (int i = tid; i < 64 * 6 * 9; i += TPB1) {
            int oc = i / 54; int r = i - oc * 54;
            int c = r / 9; int t = r - c * 9;
            sm[IW_ + ((oc >> 1) * 6 + c) * 18 + t * 2 + (oc & 1)] = w1[oc * 126 + (c + 2) * 9 + t];
        }
        if (tid < 64) {
            const float* cst = g_cst + (size_t)b * 8;
            float extra = 0.f;
            #pragma unroll
            for (int j = 0; j < 8; ++j) {
                int ic = (j < 2) ? j : (j + 6);
                const float* wb = w1 + tid * 126 + ic * 9;
                float s9 = 0.f;
                #pragma unroll
                for (int t = 0; t < 9; ++t) s9 += wb[t];
                extra += cst[j] * s9;
            }
            float s = g1[tid] * rsqrtf(v1[tid] + 1e-5f);
            sm[IE_ + tid] = s;
            sm[IE_ + 64 + tid] = s * (extra + cb1[tid] - m1[tid]) + bb1[tid];
        }
    }
    __syncthreads();

    __nv_bfloat16* xoh = g_x1h + (size_t)b * 225 * 64;
    __nv_bfloat16* xol = g_x1l + (size_t)b * 225 * 64;
    #pragma unroll
    for (int itb = 0; itb < 2; ++itb) {
        int it = tid + itb * TPB1;
        int ocg = it / 60;
        int r = it - ocg * 60;
        int pr = r >> 2, pq = r & 3;
        int x0 = 8 * pq, r0 = 2 * pr;

        u64 acc[2][2][8];
        #pragma unroll
        for (int p = 0; p < 2; ++p)
            #pragma unroll
            for (int e = 0; e < 2; ++e)
                #pragma unroll
                for (int c = 0; c < 8; ++c) acc[p][e][c] = 0ull;

        for (int ch = 0; ch < 6; ++ch) {
            const float* ib = &sm[ch * 1088 + r0 * 34 + x0];
            const u64* wb0 = (const u64*)&sm[IW_ + ((ocg * 2) * 6 + ch) * 18];
            const u64* wb1 = (const u64*)&sm[IW_ + ((ocg * 2 + 1) * 6 + ch) * 18];
            #pragma unroll
            for (int ir = 0; ir < 4; ++ir) {
                u64 d[10];
                #pragma unroll
                for (int q = 0; q < 5; ++q) {
                    float2 a = *(const float2*)(ib + ir * 34 + 2 * q);
                    d[2*q] = dup2f(a.x); d[2*q+1] = dup2f(a.y);
                }
                #pragma unroll
                for (int kx = 0; kx < 3; ++kx) {
                    if (ir <= 2) {
                        u64 wa = wb0[ir*3+kx], wc = wb1[ir*3+kx];
                        #pragma unroll
                        for (int c = 0; c < 8; ++c) { fma2(acc[0][0][c], wa, d[c+kx]); fma2(acc[1][0][c], wc, d[c+kx]); }
                    }
                    if (ir >= 1) {
                        u64 wa = wb0[(ir-1)*3+kx], wc = wb1[(ir-1)*3+kx];
                        #pragma unroll
                        for (int c = 0; c < 8; ++c) { fma2(acc[0][1][c], wa, d[c+kx]); fma2(acc[1][1][c], wc, d[c+kx]); }
                    }
                }
            }
        }
        #pragma unroll
        for (int p = 0; p < 2; ++p) {
            int oc0 = ocg * 4 + 2 * p;
            float s0 = sm[IE_+oc0], bi0 = sm[IE_+64+oc0];
            float s1 = sm[IE_+oc0+1], bi1 = sm[IE_+64+oc0+1];
            #pragma unroll
            for (int j = 0; j < 4; ++j) {
                int pt = 4 * pq + j;
                if (pt < 15) {
                    float2 a = unp2(acc[p][0][2*j]), bq = unp2(acc[p][0][2*j+1]);
                    float2 cq = unp2(acc[p][1][2*j]), e = unp2(acc[p][1][2*j+1]);
                    float v0 = fmaxf(fmaxf(fmaxf(s0*a.x+bi0,0.f), fmaxf(s0*bq.x+bi0,0.f)),
                                     fmaxf(fmaxf(s0*cq.x+bi0,0.f), fmaxf(s0*e.x+bi0,0.f)));
                    float v1_ = fmaxf(fmaxf(fmaxf(s1*a.y+bi1,0.f), fmaxf(s1*bq.y+bi1,0.f)),
                                      fmaxf(fmaxf(s1*cq.y+bi1,0.f), fmaxf(s1*e.y+bi1,0.f)));
                    int pos = pr * 15 + pt;
                    __nv_bfloat16 h0 = __float2bfloat16(v0), h1 = __float2bfloat16(v1_);
                    float r0f = v0 - __bfloat162float(h0), r1f = v1_ - __bfloat162float(h1);
                    *(unsigned*)&xoh[pos * 64 + oc0] =
                        (unsigned)__bfloat16_as_ushort(h0) | ((unsigned)__bfloat16_as_ushort(h1) << 16);
                    *(unsigned*)&xol[pos * 64 + oc0] = pack2bf(r0f, r1f);
                }
            }
        }
    }
}

// ---------------------------------------------------------------------------
// Kernel 3/4: conv 64->64, 9 tap-GEMMs, bf16 wmma 3-pass (R12 math).
// All data movement vectorized (uint4). FUSE4: conv4 + global max in-kernel.
// ---------------------------------------------------------------------------
template<int IN_W, int OUT_W, bool FUSE4, int TPB>
__global__ __launch_bounds__(TPB, 1) void convmma_kernel(
    const __nv_bfloat16* __restrict__ xinh, const __nv_bfloat16* __restrict__ xinl,
    __nv_bfloat16* __restrict__ xouth, __nv_bfloat16* __restrict__ xoutl,
    int woff,
    const float* __restrict__ cb,
    const float* __restrict__ gg, const float* __restrict__ bbv,
    const float* __restrict__ mmv, const float* __restrict__ vvv,
    const float* __restrict__ w4, const float* __restrict__ cb4,
    float* __restrict__ out)
{
    constexpr int INROWS = IN_W * IN_W;
    constexpr int MMAX = (OUT_W - 1) * IN_W + OUT_W;
    constexpr int MTILES = (MMAX + 15) / 16;
    constexpr int XROWS = ((MTILES * 16 + 2 * IN_W + 2 + 15) / 16) * 16;
    constexpr int NUNITS = MTILES * 2;       // == TPB/32
    constexpr int LDX = 72, LDW = 72;
    constexpr int OXH = 0;
    constexpr int OXL = OXH + XROWS * LDX * 2;
    constexpr int OW  = OXL + XROWS * LDX * 2;
    constexpr int OSB = OW + 9 * 64 * LDW * 2;     // W buffer: 82944 B
    constexpr int OPATCH = OW;                      // alias (post-mainloop)
    constexpr int OX3 = OW + NUNITS * 16 * 36 * 4;  // alias after patch

    extern __shared__ char smc[];
    __nv_bfloat16* Xh = (__nv_bfloat16*)(smc + OXH);
    __nv_bfloat16* Xl = (__nv_bfloat16*)(smc + OXL);
    __nv_bfloat16* Wsm = (__nv_bfloat16*)(smc + OW);
    float* sbs = (float*)(smc + OSB);
    __shared__ float ws4[576];
    __shared__ float red[32];

    const int b = blockIdx.x, tid = threadIdx.x, wid = tid >> 5, lane = tid & 31;

    // X hi/lo into smem — vectorized copy (8 bf16 per uint4)
    {
        const uint4* sh = (const uint4*)(xinh + (size_t)b * INROWS * 64);
        const uint4* sl = (const uint4*)(xinl + (size_t)b * INROWS * 64);
        for (int i = tid; i < INROWS * 8; i += TPB) {
            int p = i >> 3, c8 = (i & 7) * 8;
            *(uint4*)&Xh[p * LDX + c8] = sh[i];
            *(uint4*)&Xl[p * LDX + c8] = sl[i];
        }
        uint4 z = make_uint4(0, 0, 0, 0);
        for (int i = tid; i < (XROWS - INROWS) * 8; i += TPB) {
            int p = INROWS + (i >> 3), c8 = (i & 7) * 8;
            *(uint4*)&Xh[p * LDX + c8] = z;
            *(uint4*)&Xl[p * LDX + c8] = z;
        }
    }
    if (tid < 64) {
        float s = gg[tid] * rsqrtf(vvv[tid] + 1e-5f);
        sbs[tid] = s;
        sbs[64 + tid] = s * (cb[tid] - mmv[tid]) + bbv[tid];
    }
    // W hi (all 9 taps) — vectorized
    {
        const uint4* sh = (const uint4*)(g_wh + woff);
        for (int i = tid; i < 9 * 512; i += TPB) {
            int e = i * 8;
            int ti = e >> 12, idx = e & 4095;
            int ic = idx >> 6, c8 = idx & 63;
            *(uint4*)&Wsm[(ti * 64 + ic) * LDW + c8] = sh[i];
        }
    }
    __syncthreads();

    const int mt = wid >> 1, nh = wid & 1;

    wmma::fragment<wmma::accumulator, 16, 16, 16, float> P[2], Q[2];
    wmma::fill_fragment(P[0], 0.f); wmma::fill_fragment(P[1], 0.f);
    wmma::fill_fragment(Q[0], 0.f); wmma::fill_fragment(Q[1], 0.f);

    // ---- phase A: ah*bh -> P, al*bh -> Q ----
    #pragma unroll 1
    for (int tap = 0; tap < 9; ++tap) {
        int toff = (tap / 3) * IN_W + (tap - (tap / 3) * 3);
        const __nv_bfloat16* A0 = Xh + (mt * 16 + toff) * LDX;
        const __nv_bfloat16* A1 = Xl + (mt * 16 + toff) * LDX;
        const __nv_bfloat16* B = Wsm + (tap * 64) * LDW + nh * 32;
        #pragma unroll
        for (int k = 0; k < 4; ++k) {
            wmma::fragment<wmma::matrix_a, 16, 16, 16, __nv_bfloat16, wmma::row_major> ah, al;
            wmma::load_matrix_sync(ah, A0 + k * 16, LDX);
            wmma::load_matrix_sync(al, A1 + k * 16, LDX);
            #pragma unroll
            for (int nt = 0; nt < 2; ++nt) {
                wmma::fragment<wmma::matrix_b, 16, 16, 16, __nv_bfloat16, wmma::row_major> bh;
                wmma::load_matrix_sync(bh, B + k * 16 * LDW + nt * 16, LDW);
                wmma::mma_sync(P[nt], ah, bh, P[nt]);
                wmma::mma_sync(Q[nt], al, bh, Q[nt]);
            }
        }
    }

    // ---- swap W buffer to lo (vectorized) ----
    __syncthreads();
    {
        const uint4* sl = (const uint4*)(g_wl + woff);
        for (int i = tid; i < 9 * 512; i += TPB) {
            int e = i * 8;
            int ti = e >> 12, idx = e & 4095;
            int ic = idx >> 6, c8 = idx & 63;
            *(uint4*)&Wsm[(ti * 64 + ic) * LDW + c8] = sl[i];
        }
    }
    __syncthreads();

    // ---- phase B: ah*bl -> Q ----
    #pragma unroll 1
    for (int tap = 0; tap < 9; ++tap) {
        int toff = (tap / 3) * IN_W + (tap - (tap / 3) * 3);
        const __nv_bfloat16* A0 = Xh + (mt * 16 + toff) * LDX;
        const __nv_bfloat16* B = Wsm + (tap * 64) * LDW + nh * 32;
        #pragma unroll
        for (int k = 0; k < 4; ++k) {
            wmma::fragment<wmma::matrix_a, 16, 16, 16, __nv_bfloat16, wmma::row_major> ah;
            wmma::load_matrix_sync(ah, A0 + k * 16, LDX);
            #pragma unroll
            for (int nt = 0; nt < 2; ++nt) {
                wmma::fragment<wmma::matrix_b, 16, 16, 16, __nv_bfloat16, wmma::row_major> bl;
                wmma::load_matrix_sync(bl, B + k * 16 * LDW + nt * 16, LDW);
                wmma::mma_sync(Q[nt], ah, bl, Q[nt]);
            }
        }
    }

    // ---- merge chains ----
    #pragma unroll
    for (int nt = 0; nt < 2; ++nt)
        #pragma unroll
        for (int i = 0; i < P[nt].num_elements; ++i)
            P[nt].x[i] += Q[nt].x[i];

    // ---- epilogue (patch/x3s alias W region) ----
    __syncthreads();
    float* patch = (float*)(smc + OPATCH) + wid * 16 * 36;
    float* x3s = (float*)(smc + OX3);
    if (FUSE4)
        for (int i = tid; i < 576; i += TPB) ws4[i] = w4[i];

    {
        wmma::store_matrix_sync(patch,      P[0], 36, wmma::mem_row_major);
        wmma::store_matrix_sync(patch + 16, P[1], 36, wmma::mem_row_major);
        __syncwarp();
        int r = lane & 15, ch = (lane >> 4) * 16;
        int p = mt * 16 + r;
        int y = p / IN_W, x = p - y * IN_W;
        if (y < OUT_W && x < OUT_W) {
            int orow = y * OUT_W + x;
            if (FUSE4) {
                #pragma unroll
                for (int j = 0; j < 16; ++j) {
                    int c = nh * 32 + ch + j;
                    x3s[orow * 68 + c] = fmaxf(sbs[c] * patch[r * 36 + ch + j] + sbs[64 + c], 0.f);
                }
            } else {
                int c0 = nh * 32 + ch;
                unsigned uh[8], ul[8];
                #pragma unroll
                for (int q = 0; q < 8; ++q) {
                    int c = c0 + 2 * q;
                    float v0 = fmaxf(sbs[c] * patch[r * 36 + ch + 2*q] + sbs[64 + c], 0.f);
                    float v1_ = fmaxf(sbs[c+1] * patch[r * 36 + ch + 2*q + 1] + sbs[64 + c + 1], 0.f);
                    __nv_bfloat16 h0 = __float2bfloat16(v0), h1 = __float2bfloat16(v1_);
                    uh[q] = (unsigned)__bfloat16_as_ushort(h0) | ((unsigned)__bfloat16_as_ushort(h1) << 16);
                    ul[q] = pack2bf(v0 - __bfloat162float(h0), v1_ - __bfloat162float(h1));
                }
                uint4* dh = (uint4*)&xouth[(size_t)b * OUT_W * OUT_W * 64 + orow * 64 + c0];
                uint4* dl = (uint4*)&xoutl[(size_t)b * OUT_W * OUT_W * 64 + orow * 64 + c0];
                dh[0] = make_uint4(uh[0], uh[1], uh[2], uh[3]);
                dh[1] = make_uint4(uh[4], uh[5], uh[6], uh[7]);
                dl[0] = make_uint4(ul[0], ul[1], ul[2], ul[3]);
                dl[1] = make_uint4(ul[4], ul[5], ul[6], ul[7]);
            }
        }
        __syncwarp();
    }

    if (FUSE4) {
        __syncthreads();
        float lm = -INFINITY;
        if (tid < 81) {
            int y = tid / 9, x = tid - (tid / 9) * 9;
            float a = 0.f;
            #pragma unroll
            for (int ky = 0; ky < 3; ++ky)
                #pragma unroll
                for (int kx = 0; kx < 3; ++kx) {
                    const float* row = x3s + ((y + ky) * OUT_W + (x + kx)) * 68;
                    int t = ky * 3 + kx;
                    for (int ic = 0; ic < 64; ++ic)
                        a += row[ic] * ws4[ic * 9 + t];
                }
            lm = a;
        }
        #pragma unroll
        for (int off = 16; off > 0; off >>= 1) lm = fmaxf(lm, __shfl_xor_sync(0xffffffffu, lm, off));
        if (lane == 0) red[wid] = lm;
        __syncthreads();
        if (tid == 0) {
            float v = -INFINITY;
            for (int i = 0; i < TPB / 32; ++i) v = fmaxf(v, red[i]);
            out[b] = v + cb4[0];
        }
    }
}

// ---------------------------------------------------------------------------
extern "C" void kernel_launch(void* const* d_in, const int* in_sizes, int n_in,
                              void* d_out, int out_size)
{
    const int S2 = 152576;   // X 69120 + W 82944 + sbs 512
    const int S3 = 134144;   // X 50688 + W 82944 + sbs 512 (x3s alias OK)
    static __nv_bfloat16 *x1h = nullptr, *x1l = nullptr, *x2h = nullptr, *x2l = nullptr;
    if (!x1h) {
        cudaGetSymbolAddress((void**)&x1h, g_x1h);
        cudaGetSymbolAddress((void**)&x1l, g_x1l);
        cudaGetSymbolAddress((void**)&x2h, g_x2h);
        cudaGetSymbolAddress((void**)&x2l, g_x2l);
        cudaFuncSetAttribute(convmma_kernel<15,13,false,832>, cudaFuncAttributeMaxDynamicSharedMemorySize, S2);
        cudaFuncSetAttribute(convmma_kernel<13,11,true,576>,  cudaFuncAttributeMaxDynamicSharedMemorySize, S3);
    }

    wprep_kernel<<<288, 256>>>((const float*)d_in[11], (const float*)d_in[17]);

    stats_kernel<<<BTOT, 1024>>>(
        (const float*)d_in[0], (const float*)d_in[1],
        (const float*)d_in[2], (const float*)d_in[3], d_in[4]);

    conv1_kernel<<<BTOT, TPB1>>>(
        (const float*)d_in[5],  (const float*)d_in[6],
        (const float*)d_in[7],  (const float*)d_in[8],
        (const float*)d_in[9],  (const float*)d_in[10]);

    convmma_kernel<15,13,false,832><<<BTOT, 832, S2>>>(
        x1h, x1l, x2h, x2l, 0,
        (const float*)d_in[12],
        (const float*)d_in[13], (const float*)d_in[14],
        (const float*)d_in[15], (const float*)d_in[16],
        nullptr, nullptr, nullptr);

    convmma_kernel<13,11,true,576><<<BTOT, 576, S3>>>(
        x2h, x2l, nullptr, nullptr, 36864,
        (const float*)d_in[18],
        (const float*)d_in[19], (const float*)d_in[20],
        (const float*)d_in[21], (const float*)d_in[22],
        (const float*)d_in[23], (const float*)d_in[24],
        (float*)d_out);
}